// round 1
// baseline (speedup 1.0000x reference)
#include <cuda_runtime.h>
#include <cstdint>

// Dims: Nt=64, Nr=64, Mt=32, Mr=32, G^2=4096, num_sc=32, B=64, R=8, N_r_RF=4
#define G2 4096

// Scratch / precomputed (device globals: no allocation allowed)
__device__ float2 g_W[64 * 32];                       // W[d][m]  = exp(i kW)/8
__device__ float2 g_F[64 * 32];                       // F[c][a]  = exp(i kF)/8
__device__ float2 g_G1[(size_t)64 * 32 * 64 * 32];    // G1[b][m][c][s], 32 MB

// acc += p * q  (complex)
__device__ __forceinline__ void cmac(float2& a, float2 p, float2 q) {
    a.x = fmaf(p.x, q.x, fmaf(-p.y, q.y, a.x));
    a.y = fmaf(p.x, q.y, fmaf( p.y, q.x, a.y));
}
// acc += conj(w) * h
__device__ __forceinline__ void cmac_cj(float2& a, float2 w, float2 h) {
    a.x = fmaf(w.x, h.x, fmaf( w.y, h.y, a.x));
    a.y = fmaf(w.x, h.y, fmaf(-w.y, h.x, a.y));
}

__global__ void setup_kernel(const float* __restrict__ kW, const float* __restrict__ kF) {
    int i = blockIdx.x * blockDim.x + threadIdx.x;
    if (i < 2048) {
        float s, c;
        sincosf(kW[i], &s, &c);
        g_W[i] = make_float2(c * 0.125f, s * 0.125f);   // 1/sqrt(64)
        sincosf(kF[i], &s, &c);
        g_F[i] = make_float2(c * 0.125f, s * 0.125f);
    }
}

// Phi[a*32+b', g] = sum_c F[c,a] * ( sum_d conj(W[d,b']) * K[c*64+d, g] )
// One block per 8 consecutive g columns. 256 threads.
__global__ void __launch_bounds__(256) phi_kernel(const float2* __restrict__ K,
                                                  float2* __restrict__ Phi) {
    __shared__ float2 Ks[64][8];    // K tile: [d][g]
    __shared__ float2 Ss[8][32];    // S_c:    [g][b']
    __shared__ float2 Ws[64][32];   // W
    __shared__ float2 Fs[64][32];   // F

    const int t = threadIdx.x;
    for (int i = t; i < 2048; i += 256) {
        Ws[i >> 5][i & 31] = g_W[i];
        Fs[i >> 5][i & 31] = g_F[i];
    }

    const int g0    = blockIdx.x * 8;
    const int bp    = t & 31;        // b'
    const int gown  = t >> 5;        // g owned in S-phase / a-group in P-phase
    const int abase = gown * 4;
    const int ld_d  = t >> 2;        // load mapping: 64 d-rows x 4 float4
    const int ld_g  = (t & 3) * 2;

    float2 acc[4][8];
#pragma unroll
    for (int i = 0; i < 4; ++i)
#pragma unroll
        for (int j = 0; j < 8; ++j) acc[i][j] = make_float2(0.f, 0.f);

    __syncthreads();

    for (int c = 0; c < 64; ++c) {
        // Load K[c*64+d, g0..g0+7]: 64B contiguous per row (full sectors)
        float4 v = *reinterpret_cast<const float4*>(
            K + (size_t)(c * 64 + ld_d) * G2 + g0 + ld_g);
        Ks[ld_d][ld_g]     = make_float2(v.x, v.y);
        Ks[ld_d][ld_g + 1] = make_float2(v.z, v.w);
        __syncthreads();

        // S_c[gown][bp] = sum_d conj(W[d][bp]) * Ks[d][gown]
        {
            float2 s = make_float2(0.f, 0.f);
#pragma unroll
            for (int d = 0; d < 64; ++d) cmac_cj(s, Ws[d][bp], Ks[d][gown]);
            Ss[gown][bp] = s;
        }
        __syncthreads();

        // Phi[a][bp][g] += F[c][a] * S_c[g][bp]
#pragma unroll
        for (int aa = 0; aa < 4; ++aa) {
            float2 f = Fs[c][abase + aa];
#pragma unroll
            for (int gg = 0; gg < 8; ++gg) cmac(acc[aa][gg], f, Ss[gg][bp]);
        }
        __syncthreads();
    }

    // Write: thread owns 4 q-rows x 8 g -> 4x float4x4 contiguous 64B runs
#pragma unroll
    for (int aa = 0; aa < 4; ++aa) {
        const int q = (abase + aa) * 32 + bp;
        float4* dst = reinterpret_cast<float4*>(Phi + (size_t)q * G2 + g0);
#pragma unroll
        for (int gg = 0; gg < 4; ++gg)
            dst[gg] = make_float4(acc[aa][2 * gg].x, acc[aa][2 * gg].y,
                                  acc[aa][2 * gg + 1].x, acc[aa][2 * gg + 1].y);
    }
}

// G1[b][m][c][s] = sum_d conj(W[d][m]) * H[b][d][c][s]
// block = (b, c-tile of 8); thread owns one (c,s), accumulates all 32 m.
__global__ void __launch_bounds__(256) y1_kernel(const float2* __restrict__ H) {
    __shared__ float2 Ws[64][32];
    const int t = threadIdx.x;
    for (int i = t; i < 2048; i += 256) Ws[i >> 5][i & 31] = g_W[i];

    const int b  = blockIdx.x >> 3;
    const int ct = blockIdx.x & 7;
    const int s  = t & 31;
    const int cl = t >> 5;
    const int c  = ct * 8 + cl;

    const float2* Hp = H + ((size_t)b * 64 * 64 + c) * 32 + s;  // + d*2048

    float2 acc[32];
#pragma unroll
    for (int m = 0; m < 32; ++m) acc[m] = make_float2(0.f, 0.f);
    __syncthreads();

#pragma unroll 4
    for (int d = 0; d < 64; ++d) {
        float2 h = Hp[(size_t)d * 2048];
#pragma unroll
        for (int m = 0; m < 32; ++m) cmac_cj(acc[m], Ws[d][m], h);
    }

    float2* Gp = g_G1 + ((size_t)b * 32 * 64 + c) * 32 + s;  // + m*2048
#pragma unroll
    for (int m = 0; m < 32; ++m) Gp[(size_t)m * 2048] = acc[m];
}

// y[b, a*32 + (4r+j), s] = sum_c F[c,a]*G1[b,4r+j,c,s]
//                        + sum_n conj(W[n,4r+j])*noise[b,r,n, a*32+s]
// block = (b, r); thread owns x = t+256k (k=0..3) and j=0..3 -> 16 outputs.
__global__ void __launch_bounds__(256) y2_kernel(const float2* __restrict__ noise,
                                                 float2* __restrict__ Y) {
    __shared__ float2 Fs[64][32];
    __shared__ float2 Ws4[64][4];
    const int t = threadIdx.x;
    const int b = blockIdx.x >> 3;
    const int r = blockIdx.x & 7;

    for (int i = t; i < 2048; i += 256) Fs[i >> 5][i & 31] = g_F[i];
    {
        int n = t >> 2, j = t & 3;
        Ws4[n][j] = g_W[n * 32 + r * 4 + j];
    }
    __syncthreads();

    const int s  = t & 31;
    const int a0 = t >> 5;

    float2 acc[4][4];
#pragma unroll
    for (int k = 0; k < 4; ++k)
#pragma unroll
        for (int j = 0; j < 4; ++j) acc[k][j] = make_float2(0.f, 0.f);

    // ---- noise term: stream 512KB/block from DRAM, fully coalesced ----
    const float2* np = noise + (size_t)(b * 8 + r) * 64 * 1024 + t;
    for (int n = 0; n < 64; ++n) {
        float2 v0 = np[(size_t)n * 1024];
        float2 v1 = np[(size_t)n * 1024 + 256];
        float2 v2 = np[(size_t)n * 1024 + 512];
        float2 v3 = np[(size_t)n * 1024 + 768];
#pragma unroll
        for (int j = 0; j < 4; ++j) {
            float2 w = Ws4[n][j];
            cmac_cj(acc[0][j], w, v0);
            cmac_cj(acc[1][j], w, v1);
            cmac_cj(acc[2][j], w, v2);
            cmac_cj(acc[3][j], w, v3);
        }
    }

    // ---- signal term: contract G1 over c with F ----
    const float2* gp = g_G1 + ((size_t)b * 32 + r * 4) * 2048 + s;  // + j*2048 + c*32
    for (int c = 0; c < 64; ++c) {
        float2 gv[4];
#pragma unroll
        for (int j = 0; j < 4; ++j) gv[j] = gp[(size_t)j * 2048 + c * 32];
#pragma unroll
        for (int k = 0; k < 4; ++k) {
            float2 f = Fs[c][a0 + 8 * k];
#pragma unroll
            for (int j = 0; j < 4; ++j) cmac(acc[k][j], f, gv[j]);
        }
    }

    // write y[b][a*32 + r*4 + j][s]
#pragma unroll
    for (int k = 0; k < 4; ++k) {
        const int a = a0 + 8 * k;
        float2* yp = Y + ((size_t)b * 1024 + a * 32 + r * 4) * 32 + s;
#pragma unroll
        for (int j = 0; j < 4; ++j) yp[(size_t)j * 32] = acc[k][j];
    }
}

extern "C" void kernel_launch(void* const* d_in, const int* in_sizes, int n_in,
                              void* d_out, int out_size) {
    const float2* H     = (const float2*)d_in[0];  // (64,64,64,32,2) f32
    const float2* noise = (const float2*)d_in[1];  // (64,8,64,1024,2) f32
    const float*  kW    = (const float*)d_in[2];   // (64,32)
    const float*  kF    = (const float*)d_in[3];   // (64,32)
    const float2* K     = (const float2*)d_in[4];  // (4096,4096,2)

    float2* Phi = (float2*)d_out;                      // 1024*4096 complex
    float2* Y   = Phi + (size_t)1024 * 4096;           // 64*1024*32 complex

    setup_kernel<<<8, 256>>>(kW, kF);
    phi_kernel<<<512, 256>>>(K, Phi);
    y1_kernel<<<512, 256>>>(H);
    y2_kernel<<<512, 256>>>(noise, Y);
}